// round 13
// baseline (speedup 1.0000x reference)
#include <cuda_runtime.h>
#include <cuda_fp16.h>
#include <cstdint>

// ---------------------------------------------------------------------------
// Problem constants
// ---------------------------------------------------------------------------
#define NROWS 2048      // x rows (M)
#define DIM   1024      // K
#define SCOLS 16384     // selected neurons (N)
#define NCHUNK 4096     // N columns per overlap chunk
#define NCHUNKS (SCOLS / NCHUNK)    // 4

// GEMM tiling: CTA 128x128, 4 warps in 2x2, warp tile 64x64,
// 3-stage cp.async pipeline (distance 2), 2 CTAs/SM.
#define TM 128
#define TN 128
#define KCH 64                      // K per smem stage (64 fp16 = 128B/row)
#define KITERS (DIM / KCH)          // 16
#define NSTAGES 3
#define NTHREADS 128

#define A_BYTES (TM * 128)          // 16384
#define B_BYTES (TN * 128)          // 16384
#define STAGE_BYTES (A_BYTES + B_BYTES)       // 32768
#define SMEM_TOTAL (NSTAGES * STAGE_BYTES)    // 98304 -> 2 CTAs/SM

// ---------------------------------------------------------------------------
// Scratch (allocation-free: __device__ globals)
// ---------------------------------------------------------------------------
__device__ __align__(256) __half g_xh[(size_t)NROWS * DIM];   // 4 MiB
__device__ __align__(256) __half g_wh[(size_t)SCOLS * DIM];   // 32 MiB
__device__ __align__(256) float  g_bias[SCOLS];

// ---------------------------------------------------------------------------
// Helpers
// ---------------------------------------------------------------------------
__device__ __forceinline__ uint32_t smem_u32(const void* p) {
    uint32_t a;
    asm("{ .reg .u64 t; cvta.to.shared.u64 t, %1; cvt.u32.u64 %0, t; }"
        : "=r"(a) : "l"(p));
    return a;
}

__device__ __forceinline__ void cp16(uint32_t dst, const void* src) {
    asm volatile("cp.async.cg.shared.global [%0], [%1], 16;"
                 :: "r"(dst), "l"(src));
}

// ldmatrix with compile-time immediate byte offset (keeps address regs low)
template <int IMM>
__device__ __forceinline__ void ldmatrix_x4_i(uint32_t* r, uint32_t addr) {
    asm volatile("ldmatrix.sync.aligned.m8n8.x4.shared.b16 {%0,%1,%2,%3}, [%4+%5];"
                 : "=r"(r[0]), "=r"(r[1]), "=r"(r[2]), "=r"(r[3])
                 : "r"(addr), "n"(IMM));
}

// load 4 fragments at mt/nh strides of 16 rows (2048B), fixed immediates
__device__ __forceinline__ void load_frag4(uint32_t (*f)[4], uint32_t addr) {
    ldmatrix_x4_i<0>(f[0], addr);
    ldmatrix_x4_i<2048>(f[1], addr);
    ldmatrix_x4_i<4096>(f[2], addr);
    ldmatrix_x4_i<6144>(f[3], addr);
}

__device__ __forceinline__ void mma16816(float* c, const uint32_t* a,
                                         uint32_t b0, uint32_t b1) {
    asm volatile(
        "mma.sync.aligned.m16n8k16.row.col.f32.f16.f16.f32 "
        "{%0,%1,%2,%3}, {%4,%5,%6,%7}, {%8,%9}, {%0,%1,%2,%3};"
        : "+f"(c[0]), "+f"(c[1]), "+f"(c[2]), "+f"(c[3])
        : "r"(a[0]), "r"(a[1]), "r"(a[2]), "r"(a[3]), "r"(b0), "r"(b1));
}

// xor swizzle within a 128B-row tile: 16B-chunk ^= (row & 7)
__device__ __forceinline__ uint32_t swz(uint32_t row, uint32_t chunk) {
    return row * 128u + ((chunk ^ (row & 7u)) << 4);
}

// sample_ids dtype detection (int64 vs int32); ids < 65536 so int64 layout
// has all-odd-words zero. Reads only first 64B — safe in both layouts.
__device__ __forceinline__ long long load_id(const void* ids_raw, int s) {
    const int* i32 = (const int*)ids_raw;
    bool is64 = ((i32[1] | i32[3] | i32[5] | i32[7] |
                  i32[9] | i32[11] | i32[13] | i32[15]) == 0);
    long long id = is64 ? ((const long long*)ids_raw)[s] : (long long)i32[s];
    return id & 0xFFFFLL;   // OUT = 65536: hard OOB guard
}

// ---------------------------------------------------------------------------
// Kernel 1: prep chunk.
// Blocks [0, n_count): gather W row for column n_begin+b (f32->f16) + bias.
// Blocks [n_count, n_count+x_rows): convert one x row f32 -> f16.
// ---------------------------------------------------------------------------
__global__ void prep_kernel(const float* __restrict__ x,
                            const float* __restrict__ w,
                            const float* __restrict__ bias,
                            const void* __restrict__ ids_raw,
                            int n_begin, int n_count) {
    const int b = blockIdx.x;
    const int t = threadIdx.x;              // 128 threads, 8 f32 each
    const float4* src;
    uint4* dst;
    if (b < n_count) {
        const int col = n_begin + b;
        long long id = load_id(ids_raw, col);
        src = reinterpret_cast<const float4*>(w + (size_t)id * DIM);
        dst = reinterpret_cast<uint4*>(g_wh + (size_t)col * DIM);
        if (t == 0) g_bias[col] = bias[id];
    } else {
        const int row = b - n_count;
        src = reinterpret_cast<const float4*>(x + (size_t)row * DIM);
        dst = reinterpret_cast<uint4*>(g_xh + (size_t)row * DIM);
    }
    float4 v0 = src[2 * t];
    float4 v1 = src[2 * t + 1];
    __half2 h0 = __floats2half2_rn(v0.x, v0.y);
    __half2 h1 = __floats2half2_rn(v0.z, v0.w);
    __half2 h2 = __floats2half2_rn(v1.x, v1.y);
    __half2 h3 = __floats2half2_rn(v1.z, v1.w);
    uint4 o;
    o.x = *reinterpret_cast<uint32_t*>(&h0);
    o.y = *reinterpret_cast<uint32_t*>(&h1);
    o.z = *reinterpret_cast<uint32_t*>(&h2);
    o.w = *reinterpret_cast<uint32_t*>(&h3);
    dst[t] = o;
}

// ---------------------------------------------------------------------------
// Kernel 2: GEMM  out[m][n] = sum_k xh[m][k]*wh[n][k] + bias_sel[n]
// CTA 128x128, 4 warps (2x2), warp tile 64x64 (4x8 m16n8k16),
// 3-stage cp.async pipeline, 2 CTAs/SM. Covers columns [n_base, n_base+NCHUNK).
// ---------------------------------------------------------------------------
__global__ void __launch_bounds__(NTHREADS, 2)
gemm_kernel(float* __restrict__ out, int n_base) {
    extern __shared__ char smem[];
    const uint32_t sb = smem_u32(smem);
    const int tid = threadIdx.x;
    const int wid = tid >> 5;
    const int lid = tid & 31;
    const int wm = wid >> 1;            // 0..1  (M)
    const int wn = wid & 1;             // 0..1  (N)
    const int m0 = blockIdx.x * TM;     // 16 M-blocks (x-fastest: B L2 reuse)
    const int n0 = n_base + blockIdx.y * TN;   // 32 N-blocks per chunk

    const __half* Ag = g_xh + (size_t)m0 * DIM;
    const __half* Bg = g_wh + (size_t)n0 * DIM;

    float c[4][8][4];
#pragma unroll
    for (int i = 0; i < 4; ++i)
#pragma unroll
        for (int j = 0; j < 8; ++j)
#pragma unroll
            for (int q = 0; q < 4; ++q) c[i][j][q] = 0.f;

    const int lrow = lid & 15;
    const int lsel = lid >> 4;
    const int arow = wm * 64 + lrow;    // + mt*16 (doesn't change row&7)
    const int brow = wn * 64 + lrow;    // + nh*16 (doesn't change row&7)

    // Within-tile LDSM base offsets per k-substep (constant across kb).
    uint32_t offA[4], offB[4];
#pragma unroll
    for (int ks = 0; ks < 4; ++ks) {
        const int ch = ks * 2 + lsel;
        offA[ks] = arow * 128u + (uint32_t)((ch ^ (arow & 7)) << 4);
        offB[ks] = A_BYTES + brow * 128u + (uint32_t)((ch ^ (brow & 7)) << 4);
    }

    // Per-thread load mapping: 16 x 16B chunks per stage (A:1024, B:1024).
    auto issue_stage = [&](int kb, int slot) {
        const __half* Agk = Ag + kb * KCH;
        const __half* Bgk = Bg + kb * KCH;
        const uint32_t base = sb + slot * STAGE_BYTES;
#pragma unroll
        for (int i = 0; i < 16; ++i) {
            const int v = tid + i * NTHREADS;
            const int isB = v >> 10;
            const int vv = v & 1023;
            const int row = vv >> 3;
            const int ch = vv & 7;
            cp16(base + (isB ? A_BYTES : 0) + swz(row, ch),
                 (isB ? Bgk : Agk) + (size_t)row * DIM + ch * 8);
        }
        asm volatile("cp.async.commit_group;");
    };

    // ---- prologue: stages 0,1 ----
    issue_stage(0, 0);
    issue_stage(1, 1);

#pragma unroll 1
    for (int kb = 0; kb < KITERS; ++kb) {
        asm volatile("cp.async.wait_group 1;");   // stage kb landed
        __syncthreads();  // data visible; readers of slot (kb+2)%3 are done
        if (kb + 2 < KITERS) issue_stage(kb + 2, (kb + 2) % NSTAGES);

        const uint32_t slotbase = sb + (kb % NSTAGES) * STAGE_BYTES;

#pragma unroll
        for (int ks = 0; ks < 4; ++ks) {
            uint32_t a[4][4], b[4][4];
            load_frag4(a, slotbase + offA[ks]);
            load_frag4(b, slotbase + offB[ks]);
#pragma unroll
            for (int mt = 0; mt < 4; ++mt)
#pragma unroll
                for (int nt = 0; nt < 8; ++nt) {
                    const int nh = nt >> 1, h = nt & 1;
                    mma16816(c[mt][nt], a[mt], b[nh][h], b[nh][2 + h]);
                }
        }
        // no trailing barrier: next iteration's __syncthreads provides the
        // read-complete guarantee before slot reuse.
    }

    // ---- epilogue: += bias, write f32 ----
    const int g = lid >> 2, t = lid & 3;
    const int ncol = n0 + wn * 64 + t * 2;
    float2 bias2[8];
#pragma unroll
    for (int nt = 0; nt < 8; ++nt) {
        bias2[nt].x = g_bias[ncol + nt * 8];
        bias2[nt].y = g_bias[ncol + nt * 8 + 1];
    }
#pragma unroll
    for (int mt = 0; mt < 4; ++mt) {
        const int r0 = m0 + wm * 64 + mt * 16 + g;
        float* p0 = out + (size_t)r0 * SCOLS + ncol;
        float* p1 = p0 + (size_t)8 * SCOLS;
#pragma unroll
        for (int nt = 0; nt < 8; ++nt) {
            float2 v0 = {c[mt][nt][0] + bias2[nt].x, c[mt][nt][1] + bias2[nt].y};
            float2 v1 = {c[mt][nt][2] + bias2[nt].x, c[mt][nt][3] + bias2[nt].y};
            *reinterpret_cast<float2*>(p0 + nt * 8) = v0;
            *reinterpret_cast<float2*>(p1 + nt * 8) = v1;
        }
    }
}

// ---------------------------------------------------------------------------
// kernel_launch
// inputs (metadata order): x f32[2048*1024], weight f32[65536*1024],
//                          bias f32[65536], sample_ids int (32 or 64)[16384]
// output: f32[2048*16384]
//
// Overlap structure (all ops graph-capturable; events/streams become graph
// edges): default stream runs the 4 prep chunks; non-blocking stream s1 runs
// the 4 GEMM chunks, each gated on its prep via event. Final event joins s1
// back to the default stream.
// ---------------------------------------------------------------------------
extern "C" void kernel_launch(void* const* d_in, const int* in_sizes, int n_in,
                              void* d_out, int out_size) {
    const float* x = (const float*)d_in[0];
    const float* w = (const float*)d_in[1];
    const float* bias = (const float*)d_in[2];
    const void* ids = d_in[3];
    float* out = (float*)d_out;

    static bool init = false;
    static cudaStream_t s1 = 0;
    static cudaEvent_t ev[NCHUNKS + 1];
    if (!init) {
        init = true;
        if (cudaStreamCreateWithFlags(&s1, cudaStreamNonBlocking) != cudaSuccess)
            s1 = 0;
        for (int i = 0; i <= NCHUNKS; ++i)
            cudaEventCreateWithFlags(&ev[i], cudaEventDisableTiming);
        cudaFuncSetAttribute(gemm_kernel,
                             cudaFuncAttributeMaxDynamicSharedMemorySize,
                             SMEM_TOTAL);
    }

    const dim3 grid(NROWS / TM, NCHUNK / TN);   // (16, 32) per chunk

    if (s1) {
        for (int ck = 0; ck < NCHUNKS; ++ck) {
            // prep chunk ck on default stream (chunk 0 also converts x)
            const int extra = (ck == 0) ? NROWS : 0;
            prep_kernel<<<NCHUNK + extra, 128>>>(x, w, bias, ids,
                                                 ck * NCHUNK, NCHUNK);
            cudaEventRecord(ev[ck], 0);
            cudaStreamWaitEvent(s1, ev[ck], 0);
            gemm_kernel<<<grid, NTHREADS, SMEM_TOTAL, s1>>>(out, ck * NCHUNK);
        }
        cudaEventRecord(ev[NCHUNKS], s1);
        cudaStreamWaitEvent(0, ev[NCHUNKS], 0);   // join back
    } else {
        // fallback: sequential on the default stream
        for (int ck = 0; ck < NCHUNKS; ++ck) {
            const int extra = (ck == 0) ? NROWS : 0;
            prep_kernel<<<NCHUNK + extra, 128>>>(x, w, bias, ids,
                                                 ck * NCHUNK, NCHUNK);
        }
        for (int ck = 0; ck < NCHUNKS; ++ck)
            gemm_kernel<<<grid, NTHREADS, SMEM_TOTAL>>>(out, ck * NCHUNK);
    }
}

// round 14
// speedup vs baseline: 1.1213x; 1.1213x over previous
#include <cuda_runtime.h>
#include <cuda_fp16.h>
#include <cstdint>

// ---------------------------------------------------------------------------
// Problem constants
// ---------------------------------------------------------------------------
#define NROWS 2048      // x rows (M)
#define DIM   1024      // K
#define SCOLS 16384     // selected neurons (N)

// GEMM tiling: CTA 128x128, 4 warps in 2x2, warp tile 64x64,
// 3-stage cp.async pipeline (distance 2), 2 CTAs/SM.  (= R9, best known)
#define TM 128
#define TN 128
#define KCH 64                      // K per smem stage (64 fp16 = 128B/row)
#define KITERS (DIM / KCH)          // 16
#define NSTAGES 3
#define NTHREADS 128

#define A_BYTES (TM * 128)          // 16384
#define B_BYTES (TN * 128)          // 16384
#define STAGE_BYTES (A_BYTES + B_BYTES)       // 32768
#define SMEM_TOTAL (NSTAGES * STAGE_BYTES)    // 98304 -> 2 CTAs/SM

// ---------------------------------------------------------------------------
// Scratch (allocation-free: __device__ globals)
// ---------------------------------------------------------------------------
__device__ __align__(256) __half g_xh[(size_t)NROWS * DIM];   // 4 MiB
__device__ __align__(256) __half g_wh[(size_t)SCOLS * DIM];   // 32 MiB
__device__ __align__(256) float  g_bias[SCOLS];

// ---------------------------------------------------------------------------
// Helpers
// ---------------------------------------------------------------------------
__device__ __forceinline__ uint32_t smem_u32(const void* p) {
    uint32_t a;
    asm("{ .reg .u64 t; cvta.to.shared.u64 t, %1; cvt.u32.u64 %0, t; }"
        : "=r"(a) : "l"(p));
    return a;
}

__device__ __forceinline__ void cp16(uint32_t dst, const void* src) {
    asm volatile("cp.async.cg.shared.global [%0], [%1], 16;"
                 :: "r"(dst), "l"(src));
}

__device__ __forceinline__ void ldmatrix_x4(uint32_t* r, uint32_t addr) {
    asm volatile("ldmatrix.sync.aligned.m8n8.x4.shared.b16 {%0,%1,%2,%3}, [%4];"
                 : "=r"(r[0]), "=r"(r[1]), "=r"(r[2]), "=r"(r[3])
                 : "r"(addr));
}

__device__ __forceinline__ void mma16816(float* c, const uint32_t* a,
                                         uint32_t b0, uint32_t b1) {
    asm volatile(
        "mma.sync.aligned.m16n8k16.row.col.f32.f16.f16.f32 "
        "{%0,%1,%2,%3}, {%4,%5,%6,%7}, {%8,%9}, {%0,%1,%2,%3};"
        : "+f"(c[0]), "+f"(c[1]), "+f"(c[2]), "+f"(c[3])
        : "r"(a[0]), "r"(a[1]), "r"(a[2]), "r"(a[3]), "r"(b0), "r"(b1));
}

// streaming (evict-first) 16B global load: read-once data, keep L2 for g_wh
__device__ __forceinline__ float4 ldg_cs4(const float4* p) {
    float4 v;
    asm volatile("ld.global.cs.v4.f32 {%0,%1,%2,%3}, [%4];"
                 : "=f"(v.x), "=f"(v.y), "=f"(v.z), "=f"(v.w) : "l"(p));
    return v;
}

// xor swizzle within a 128B-row tile: 16B-chunk ^= (row & 7)
__device__ __forceinline__ uint32_t swz(uint32_t row, uint32_t chunk) {
    return row * 128u + ((chunk ^ (row & 7u)) << 4);
}

// sample_ids dtype detection (int64 vs int32); ids < 65536 so int64 layout
// has all-odd-words zero. Reads only first 64B — safe in both layouts.
__device__ __forceinline__ long long load_id(const void* ids_raw, int s) {
    const int* i32 = (const int*)ids_raw;
    bool is64 = ((i32[1] | i32[3] | i32[5] | i32[7] |
                  i32[9] | i32[11] | i32[13] | i32[15]) == 0);
    long long id = is64 ? ((const long long*)ids_raw)[s] : (long long)i32[s];
    return id & 0xFFFFLL;   // OUT = 65536: hard OOB guard
}

// ---------------------------------------------------------------------------
// Kernel 1 (fused): blocks [0, SCOLS): gather W[sample_ids] -> g_wh (f16) and
// bias; blocks [SCOLS, SCOLS+NROWS): convert one x row f32 -> f16.
// 128 threads: each converts 8 floats (2 float4 -> 1 uint4 = STG.128).
// Source reads use .cs (read-once, evict-first) to keep L2 for g_wh/g_xh.
// ---------------------------------------------------------------------------
__global__ void prep_kernel(const float* __restrict__ x,
                            const float* __restrict__ w,
                            const float* __restrict__ bias,
                            const void* __restrict__ ids_raw) {
    const int b = blockIdx.x;
    const int t = threadIdx.x;              // 128 threads, 8 f32 each
    const float4* src;
    uint4* dst;
    if (b < SCOLS) {
        long long id = load_id(ids_raw, b);
        src = reinterpret_cast<const float4*>(w + (size_t)id * DIM);
        dst = reinterpret_cast<uint4*>(g_wh + (size_t)b * DIM);
        if (t == 0) g_bias[b] = bias[id];
    } else {
        const int row = b - SCOLS;
        src = reinterpret_cast<const float4*>(x + (size_t)row * DIM);
        dst = reinterpret_cast<uint4*>(g_xh + (size_t)row * DIM);
    }
    float4 v0 = ldg_cs4(src + 2 * t);
    float4 v1 = ldg_cs4(src + 2 * t + 1);
    __half2 h0 = __floats2half2_rn(v0.x, v0.y);
    __half2 h1 = __floats2half2_rn(v0.z, v0.w);
    __half2 h2 = __floats2half2_rn(v1.x, v1.y);
    __half2 h3 = __floats2half2_rn(v1.z, v1.w);
    uint4 o;
    o.x = *reinterpret_cast<uint32_t*>(&h0);
    o.y = *reinterpret_cast<uint32_t*>(&h1);
    o.z = *reinterpret_cast<uint32_t*>(&h2);
    o.w = *reinterpret_cast<uint32_t*>(&h3);
    dst[t] = o;
}

// ---------------------------------------------------------------------------
// Kernel 2: GEMM  out[m][n] = sum_k xh[m][k]*wh[n][k] + bias_sel[n]
// CTA 128x128, 4 warps (2x2), warp tile 64x64 (4x8 m16n8k16),
// 3-stage cp.async pipeline, 2 CTAs/SM.  (= R9 verbatim, 198.1 us)
// ---------------------------------------------------------------------------
__global__ void __launch_bounds__(NTHREADS, 2)
gemm_kernel(float* __restrict__ out) {
    extern __shared__ char smem[];
    const uint32_t sb = smem_u32(smem);
    const int tid = threadIdx.x;
    const int wid = tid >> 5;
    const int lid = tid & 31;
    const int wm = wid >> 1;            // 0..1  (M)
    const int wn = wid & 1;             // 0..1  (N)
    const int m0 = blockIdx.x * TM;     // 16 M-blocks (x-fastest: B L2 reuse)
    const int n0 = blockIdx.y * TN;     // 128 N-blocks

    const __half* Ag = g_xh + (size_t)m0 * DIM;
    const __half* Bg = g_wh + (size_t)n0 * DIM;

    float c[4][8][4];
#pragma unroll
    for (int i = 0; i < 4; ++i)
#pragma unroll
        for (int j = 0; j < 8; ++j)
#pragma unroll
            for (int q = 0; q < 4; ++q) c[i][j][q] = 0.f;

    const int lrow = lid & 15;
    const int lsel = lid >> 4;
    const int arow = wm * 64 + lrow;    // + mt*16
    const int brow = wn * 64 + lrow;    // + nh*16

    // Per-thread load mapping: 16 x 16B chunks per stage (A:1024, B:1024).
    auto issue_stage = [&](int kb, int slot) {
        const __half* Agk = Ag + kb * KCH;
        const __half* Bgk = Bg + kb * KCH;
        const uint32_t base = sb + slot * STAGE_BYTES;
#pragma unroll
        for (int i = 0; i < 16; ++i) {
            const int v = tid + i * NTHREADS;
            const int isB = v >> 10;
            const int vv = v & 1023;
            const int row = vv >> 3;
            const int ch = vv & 7;
            cp16(base + (isB ? A_BYTES : 0) + swz(row, ch),
                 (isB ? Bgk : Agk) + (size_t)row * DIM + ch * 8);
        }
        asm volatile("cp.async.commit_group;");
    };

    // ---- prologue: stages 0,1 ----
    issue_stage(0, 0);
    issue_stage(1, 1);

#pragma unroll 1
    for (int kb = 0; kb < KITERS; ++kb) {
        asm volatile("cp.async.wait_group 1;");   // stage kb landed
        __syncthreads();  // data visible; readers of slot (kb+2)%3 are done
        if (kb + 2 < KITERS) issue_stage(kb + 2, (kb + 2) % NSTAGES);

        const uint32_t abase = sb + (kb % NSTAGES) * STAGE_BYTES;
        const uint32_t bbase = abase + A_BYTES;

#pragma unroll
        for (int ks = 0; ks < 4; ++ks) {
            const int ch = ks * 2 + lsel;
            uint32_t a[4][4];
#pragma unroll
            for (int mt = 0; mt < 4; ++mt)
                ldmatrix_x4(a[mt], abase + swz(arow + mt * 16, ch));
            uint32_t b[4][4];
#pragma unroll
            for (int nh = 0; nh < 4; ++nh)
                ldmatrix_x4(b[nh], bbase + swz(brow + nh * 16, ch));
#pragma unroll
            for (int mt = 0; mt < 4; ++mt)
#pragma unroll
                for (int nt = 0; nt < 8; ++nt) {
                    const int nh = nt >> 1, h = nt & 1;
                    mma16816(c[mt][nt], a[mt], b[nh][h], b[nh][2 + h]);
                }
        }
        // no trailing barrier: next iteration's __syncthreads provides the
        // read-complete guarantee before slot reuse.
    }

    // ---- epilogue: += bias, write f32 ----
    const int g = lid >> 2, t = lid & 3;
    const int ncol = n0 + wn * 64 + t * 2;
    float2 bias2[8];
#pragma unroll
    for (int nt = 0; nt < 8; ++nt) {
        bias2[nt].x = g_bias[ncol + nt * 8];
        bias2[nt].y = g_bias[ncol + nt * 8 + 1];
    }
#pragma unroll
    for (int mt = 0; mt < 4; ++mt) {
        const int r0 = m0 + wm * 64 + mt * 16 + g;
        float* p0 = out + (size_t)r0 * SCOLS + ncol;
        float* p1 = p0 + (size_t)8 * SCOLS;
#pragma unroll
        for (int nt = 0; nt < 8; ++nt) {
            float2 v0 = {c[mt][nt][0] + bias2[nt].x, c[mt][nt][1] + bias2[nt].y};
            float2 v1 = {c[mt][nt][2] + bias2[nt].x, c[mt][nt][3] + bias2[nt].y};
            *reinterpret_cast<float2*>(p0 + nt * 8) = v0;
            *reinterpret_cast<float2*>(p1 + nt * 8) = v1;
        }
    }
}

// ---------------------------------------------------------------------------
// kernel_launch
// inputs (metadata order): x f32[2048*1024], weight f32[65536*1024],
//                          bias f32[65536], sample_ids int (32 or 64)[16384]
// output: f32[2048*16384]
// ---------------------------------------------------------------------------
extern "C" void kernel_launch(void* const* d_in, const int* in_sizes, int n_in,
                              void* d_out, int out_size) {
    const float* x = (const float*)d_in[0];
    const float* w = (const float*)d_in[1];
    const float* bias = (const float*)d_in[2];
    const void* ids = d_in[3];
    float* out = (float*)d_out;

    cudaFuncSetAttribute(gemm_kernel,
                         cudaFuncAttributeMaxDynamicSharedMemorySize, SMEM_TOTAL);

    prep_kernel<<<SCOLS + NROWS, 128>>>(x, w, bias, ids);
    dim3 grid(NROWS / TM, SCOLS / TN);      // (16, 128)
    gemm_kernel<<<grid, NTHREADS, SMEM_TOTAL>>>(out);
}

// round 15
// speedup vs baseline: 1.1441x; 1.0203x over previous
#include <cuda_runtime.h>
#include <cuda_fp16.h>
#include <cstdint>

// ---------------------------------------------------------------------------
// Problem constants
// ---------------------------------------------------------------------------
#define NROWS 2048      // x rows (M)
#define DIM   1024      // K
#define SCOLS 16384     // selected neurons (N)

// GEMM tiling: CTA 128x128, 4 warps in 2x2, warp tile 64x64,
// 3-stage cp.async pipeline (distance 2), 2 CTAs/SM.  (= R9/R14 core)
#define TM 128
#define TN 128
#define KCH 64                      // K per smem stage (64 fp16 = 128B/row)
#define KITERS (DIM / KCH)          // 16
#define NSTAGES 3
#define NTHREADS 128

#define A_BYTES (TM * 128)          // 16384
#define B_BYTES (TN * 128)          // 16384
#define STAGE_BYTES (A_BYTES + B_BYTES)       // 32768
#define SMEM_TOTAL (NSTAGES * STAGE_BYTES)    // 98304 -> 2 CTAs/SM

// ---------------------------------------------------------------------------
// Scratch (allocation-free: __device__ globals)
// ---------------------------------------------------------------------------
__device__ __align__(256) __half g_xh[(size_t)NROWS * DIM];   // 4 MiB
__device__ __align__(256) __half g_wh[(size_t)SCOLS * DIM];   // 32 MiB
__device__ __align__(256) float  g_bias[SCOLS];

// ---------------------------------------------------------------------------
// Helpers
// ---------------------------------------------------------------------------
__device__ __forceinline__ uint32_t smem_u32(const void* p) {
    uint32_t a;
    asm("{ .reg .u64 t; cvta.to.shared.u64 t, %1; cvt.u32.u64 %0, t; }"
        : "=r"(a) : "l"(p));
    return a;
}

__device__ __forceinline__ void cp16(uint32_t dst, const void* src) {
    asm volatile("cp.async.cg.shared.global [%0], [%1], 16;"
                 :: "r"(dst), "l"(src));
}

// ldmatrix with compile-time immediate byte offset (keeps address regs low)
template <int IMM>
__device__ __forceinline__ void ldmatrix_x4_i(uint32_t* r, uint32_t addr) {
    asm volatile("ldmatrix.sync.aligned.m8n8.x4.shared.b16 {%0,%1,%2,%3}, [%4+%5];"
                 : "=r"(r[0]), "=r"(r[1]), "=r"(r[2]), "=r"(r[3])
                 : "r"(addr), "n"(IMM));
}

// load 4 fragments at mt/nh strides of 16 rows (2048B), fixed immediates
__device__ __forceinline__ void load_frag4(uint32_t (*f)[4], uint32_t addr) {
    ldmatrix_x4_i<0>(f[0], addr);
    ldmatrix_x4_i<2048>(f[1], addr);
    ldmatrix_x4_i<4096>(f[2], addr);
    ldmatrix_x4_i<6144>(f[3], addr);
}

__device__ __forceinline__ void mma16816(float* c, const uint32_t* a,
                                         uint32_t b0, uint32_t b1) {
    asm volatile(
        "mma.sync.aligned.m16n8k16.row.col.f32.f16.f16.f32 "
        "{%0,%1,%2,%3}, {%4,%5,%6,%7}, {%8,%9}, {%0,%1,%2,%3};"
        : "+f"(c[0]), "+f"(c[1]), "+f"(c[2]), "+f"(c[3])
        : "r"(a[0]), "r"(a[1]), "r"(a[2]), "r"(a[3]), "r"(b0), "r"(b1));
}

// streaming (evict-first) 16B global load: read-once data, keep L2 for g_wh
__device__ __forceinline__ float4 ldg_cs4(const float4* p) {
    float4 v;
    asm volatile("ld.global.cs.v4.f32 {%0,%1,%2,%3}, [%4];"
                 : "=f"(v.x), "=f"(v.y), "=f"(v.z), "=f"(v.w) : "l"(p));
    return v;
}

// streaming 8B global store (write-once output; don't evict B tiles from L2)
__device__ __forceinline__ void stg_cs2(float* p, float vx, float vy) {
    asm volatile("st.global.cs.v2.f32 [%0], {%1,%2};"
                 :: "l"(p), "f"(vx), "f"(vy) : "memory");
}

// xor swizzle within a 128B-row tile: 16B-chunk ^= (row & 7)
__device__ __forceinline__ uint32_t swz(uint32_t row, uint32_t chunk) {
    return row * 128u + ((chunk ^ (row & 7u)) << 4);
}

// sample_ids dtype detection (int64 vs int32); ids < 65536 so int64 layout
// has all-odd-words zero. Reads only first 64B — safe in both layouts.
__device__ __forceinline__ long long load_id(const void* ids_raw, int s) {
    const int* i32 = (const int*)ids_raw;
    bool is64 = ((i32[1] | i32[3] | i32[5] | i32[7] |
                  i32[9] | i32[11] | i32[13] | i32[15]) == 0);
    long long id = is64 ? ((const long long*)ids_raw)[s] : (long long)i32[s];
    return id & 0xFFFFLL;   // OUT = 65536: hard OOB guard
}

// ---------------------------------------------------------------------------
// Kernel 1 (fused): blocks [0, SCOLS): gather W[sample_ids] -> g_wh (f16) and
// bias; blocks [SCOLS, SCOLS+NROWS): convert one x row f32 -> f16.
// Source reads use .cs (read-once, evict-first) to keep L2 for g_wh/g_xh.
// ---------------------------------------------------------------------------
__global__ void prep_kernel(const float* __restrict__ x,
                            const float* __restrict__ w,
                            const float* __restrict__ bias,
                            const void* __restrict__ ids_raw) {
    const int b = blockIdx.x;
    const int t = threadIdx.x;              // 128 threads, 8 f32 each
    const float4* src;
    uint4* dst;
    if (b < SCOLS) {
        long long id = load_id(ids_raw, b);
        src = reinterpret_cast<const float4*>(w + (size_t)id * DIM);
        dst = reinterpret_cast<uint4*>(g_wh + (size_t)b * DIM);
        if (t == 0) g_bias[b] = bias[id];
    } else {
        const int row = b - SCOLS;
        src = reinterpret_cast<const float4*>(x + (size_t)row * DIM);
        dst = reinterpret_cast<uint4*>(g_xh + (size_t)row * DIM);
    }
    float4 v0 = ldg_cs4(src + 2 * t);
    float4 v1 = ldg_cs4(src + 2 * t + 1);
    __half2 h0 = __floats2half2_rn(v0.x, v0.y);
    __half2 h1 = __floats2half2_rn(v0.z, v0.w);
    __half2 h2 = __floats2half2_rn(v1.x, v1.y);
    __half2 h3 = __floats2half2_rn(v1.z, v1.w);
    uint4 o;
    o.x = *reinterpret_cast<uint32_t*>(&h0);
    o.y = *reinterpret_cast<uint32_t*>(&h1);
    o.z = *reinterpret_cast<uint32_t*>(&h2);
    o.w = *reinterpret_cast<uint32_t*>(&h3);
    dst[t] = o;
}

// ---------------------------------------------------------------------------
// Kernel 2: GEMM  out[m][n] = sum_k xh[m][k]*wh[n][k] + bias_sel[n]
// CTA 128x128, 4 warps (2x2), warp tile 64x64 (4x8 m16n8k16),
// 3-stage cp.async pipeline, 2 CTAs/SM. Hoisted addressing.
// ---------------------------------------------------------------------------
__global__ void __launch_bounds__(NTHREADS, 2)
gemm_kernel(float* __restrict__ out) {
    extern __shared__ char smem[];
    const uint32_t sb = smem_u32(smem);
    const int tid = threadIdx.x;
    const int wid = tid >> 5;
    const int lid = tid & 31;
    const int wm = wid >> 1;            // 0..1  (M)
    const int wn = wid & 1;             // 0..1  (N)
    const int m0 = blockIdx.x * TM;     // 16 M-blocks (x-fastest: B L2 reuse)
    const int n0 = blockIdx.y * TN;     // 128 N-blocks

    // ---- hoisted cp.async addressing ----
    // chunk index v = tid + i*128: i<8 -> A (row=(tid>>3)+16i), i>=8 -> B
    // (row=(tid>>3)+16(i-8)); ch = tid&7 and row&7 = (tid>>3)&7 for ALL i,
    // so the swizzle XOR is one per-thread constant.
    const int trow = tid >> 3;          // 0..15
    const int tch = tid & 7;
    const uint32_t soff =               // within-tile smem offset, chunk 0
        (uint32_t)trow * 128u + (uint32_t)((tch ^ (trow & 7)) << 4);
    const __half* srcA0 = g_xh + (size_t)(m0 + trow) * DIM + tch * 8;
    const __half* srcB0 = g_wh + (size_t)(n0 + trow) * DIM + tch * 8;

    auto issue_stage = [&](int kb, int slot) {
        const uint32_t dstA = sb + slot * STAGE_BYTES + soff;
        const __half* sA = srcA0 + kb * KCH;
        const __half* sB = srcB0 + kb * KCH;
#pragma unroll
        for (int i = 0; i < 8; ++i)
            cp16(dstA + i * 2048, sA + (size_t)(16 * i) * DIM);
#pragma unroll
        for (int i = 0; i < 8; ++i)
            cp16(dstA + A_BYTES + i * 2048, sB + (size_t)(16 * i) * DIM);
        asm volatile("cp.async.commit_group;");
    };

    float c[4][8][4];
#pragma unroll
    for (int i = 0; i < 4; ++i)
#pragma unroll
        for (int j = 0; j < 8; ++j)
#pragma unroll
            for (int q = 0; q < 4; ++q) c[i][j][q] = 0.f;

    const int lrow = lid & 15;
    const int lsel = lid >> 4;
    const int arow = wm * 64 + lrow;    // + mt*16 (row&7 invariant)
    const int brow = wn * 64 + lrow;    // + nh*16 (row&7 invariant)

    // Per-ks LDSM base offsets (mt/nh handled by +2048 immediates).
    uint32_t offA[4], offB[4];
#pragma unroll
    for (int ks = 0; ks < 4; ++ks) {
        const int ch = ks * 2 + lsel;
        offA[ks] = arow * 128u + (uint32_t)((ch ^ (arow & 7)) << 4);
        offB[ks] = A_BYTES + brow * 128u + (uint32_t)((ch ^ (brow & 7)) << 4);
    }

    // ---- prologue: stages 0,1 ----
    issue_stage(0, 0);
    issue_stage(1, 1);

#pragma unroll 1
    for (int kb = 0; kb < KITERS; ++kb) {
        asm volatile("cp.async.wait_group 1;");   // stage kb landed
        __syncthreads();  // data visible; readers of slot (kb+2)%3 are done
        if (kb + 2 < KITERS) issue_stage(kb + 2, (kb + 2) % NSTAGES);

        const uint32_t slotbase = sb + (kb % NSTAGES) * STAGE_BYTES;

#pragma unroll
        for (int ks = 0; ks < 4; ++ks) {
            uint32_t a[4][4], b[4][4];
            load_frag4(a, slotbase + offA[ks]);
            load_frag4(b, slotbase + offB[ks]);
#pragma unroll
            for (int mt = 0; mt < 4; ++mt)
#pragma unroll
                for (int nt = 0; nt < 8; ++nt) {
                    const int nh = nt >> 1, h = nt & 1;
                    mma16816(c[mt][nt], a[mt], b[nh][h], b[nh][2 + h]);
                }
        }
        // no trailing barrier: next iteration's __syncthreads provides the
        // read-complete guarantee before slot reuse.
    }

    // ---- epilogue: += bias, streaming f32 stores ----
    const int g = lid >> 2, t = lid & 3;
    const int ncol = n0 + wn * 64 + t * 2;
    float2 bias2[8];
#pragma unroll
    for (int nt = 0; nt < 8; ++nt) {
        bias2[nt].x = g_bias[ncol + nt * 8];
        bias2[nt].y = g_bias[ncol + nt * 8 + 1];
    }
#pragma unroll
    for (int mt = 0; mt < 4; ++mt) {
        const int r0 = m0 + wm * 64 + mt * 16 + g;
        float* p0 = out + (size_t)r0 * SCOLS + ncol;
        float* p1 = p0 + (size_t)8 * SCOLS;
#pragma unroll
        for (int nt = 0; nt < 8; ++nt) {
            stg_cs2(p0 + nt * 8, c[mt][nt][0] + bias2[nt].x,
                                 c[mt][nt][1] + bias2[nt].y);
            stg_cs2(p1 + nt * 8, c[mt][nt][2] + bias2[nt].x,
                                 c[mt][nt][3] + bias2[nt].y);
        }
    }
}

// ---------------------------------------------------------------------------
// kernel_launch
// inputs (metadata order): x f32[2048*1024], weight f32[65536*1024],
//                          bias f32[65536], sample_ids int (32 or 64)[16384]
// output: f32[2048*16384]
// ---------------------------------------------------------------------------
extern "C" void kernel_launch(void* const* d_in, const int* in_sizes, int n_in,
                              void* d_out, int out_size) {
    const float* x = (const float*)d_in[0];
    const float* w = (const float*)d_in[1];
    const float* bias = (const float*)d_in[2];
    const void* ids = d_in[3];
    float* out = (float*)d_out;

    cudaFuncSetAttribute(gemm_kernel,
                         cudaFuncAttributeMaxDynamicSharedMemorySize, SMEM_TOTAL);

    prep_kernel<<<SCOLS + NROWS, 128>>>(x, w, bias, ids);
    dim3 grid(NROWS / TM, SCOLS / TN);      // (16, 128)
    gemm_kernel<<<grid, NTHREADS, SMEM_TOTAL>>>(out);
}